// round 13
// baseline (speedup 1.0000x reference)
#include <cuda_runtime.h>
#include <math.h>

#define NC 16
#define MARGIN 0.3f
#define EPS 1e-8f
#define INVALID 0x7fffffff
#define NBIN 4096            // 16^3 class combos
#define NPAIR 120            // 16*15/2 unordered pairs
#define TPT 16               // triples per hist thread

// ---------------- device-global scratch (zero-init; finalizer resets) ----------
__device__ int      g_hist[NBIN];
__device__ float    g_D[NC * NC];
__device__ int      g_present[NC];
__device__ unsigned g_done;

// Dedup-min: within one load slot the global index rises with lane, so the
// lowest-lane peer holding a given class value owns the warp minimum.
__device__ __forceinline__ void first_update(unsigned w, int i, int* s_first) {
    unsigned peers = __match_any_sync(0xffffffffu, w);
    int leader = __ffs(peers) - 1;
    if (((int)(threadIdx.x & 31) == leader) && w < (unsigned)NC)
        atomicMin(&s_first[w], i);
}

// ONE kernel, DISJOINT block roles. Finalizer (the last block to finish)
// FRONT-BATCHES all its global reads into registers before touching g_hist
// with stores — the load->use->store-per-iteration loop of R9..R11 serialized
// 16 L2 round-trips and was the hidden ~12us tail.
__global__ __launch_bounds__(256) void fused(
    const float* __restrict__ inputs, const void* __restrict__ tm,
    const void* __restrict__ ua, int n_tm, int T, int D,
    int nblocks, float* __restrict__ out)
{
    __shared__ int   sH[NBIN];             // hist role only (16 KB)
    __shared__ int   s_first[NC];          // pair role; reused as sP in finalize
    __shared__ int   s_nz, s_last;
    __shared__ float s_part[8];
    __shared__ float sDf[NC * NC];
    __shared__ float srk[8], spr[8], scv[8];

    const int tid = threadIdx.x;
    const int bid = blockIdx.x;

    if (tid == 0) { s_nz = 0; s_last = 0; }

    if (bid < NPAIR) {
        // ================= PAIR ROLE (kA's proven block body) =================
        if (tid < NC) s_first[tid] = INVALID;
        __syncthreads();

        const unsigned* tw = (const unsigned*)tm;

        unsigned det = 0u;
        {
            int w0 = 2 * tid + 1;
            if (w0 < n_tm) det = tw[w0];
            int w1 = w0 + 512;
            if (w1 < n_tm) det |= tw[w1];
        }
        unsigned wv[16];
        #pragma unroll
        for (int r = 0; r < 16; r++) {
            int i = r * 256 + tid;
            wv[r] = (i < n_tm) ? tw[i] : ~0u;
        }
        if (det) s_nz = 1;
        __syncthreads();

        if (s_nz) {          // int32: speculative loads are the real data
            #pragma unroll
            for (int r = 0; r < 16; r++) first_update(wv[r], r * 256 + tid, s_first);
            for (int i = 4096 + tid; i < n_tm; i += 256)
                first_update(tw[i], i, s_first);
        } else {             // int64: low words at stride 2
            for (int i = tid; i < n_tm; i += 256)
                first_update(tw[2 * i], i, s_first);
        }
        __syncthreads();

        int b = bid, pi = 0, rem = b, cnt = NC - 1;
        while (rem >= cnt) { rem -= cnt; cnt--; pi++; }
        int pj = pi + 1 + rem;
        int fi = s_first[pi]; if (fi == INVALID) fi = 0;   // argmax all-false==0
        int fj = s_first[pj]; if (fj == INVALID) fj = 0;

        float acc = 0.0f;
        const float* ra = inputs + (size_t)fi * D;
        const float* rb = inputs + (size_t)fj * D;
        for (int base = 0; base < D; base += 1024) {
            int k = base + tid * 4;
            if (k + 4 <= D) {
                float4 x = __ldg((const float4*)(ra + k));
                float4 y = __ldg((const float4*)(rb + k));
                float d0 = x.x - y.x, d1 = x.y - y.y;
                float d2 = x.z - y.z, d3 = x.w - y.w;
                acc = fmaf(d0, d0, acc); acc = fmaf(d1, d1, acc);
                acc = fmaf(d2, d2, acc); acc = fmaf(d3, d3, acc);
            } else {
                for (int q = k; q < D && q < k + 4; q++) {
                    float d = __ldg(ra + q) - __ldg(rb + q);
                    acc = fmaf(d, d, acc);
                }
            }
        }
        #pragma unroll
        for (int o = 16; o > 0; o >>= 1) acc += __shfl_xor_sync(~0u, acc, o);
        if ((tid & 31) == 0) s_part[tid >> 5] = acc;
        __syncthreads();
        if (tid == 0) {
            float s = 0.0f;
            #pragma unroll
            for (int k = 0; k < 8; k++) s += s_part[k];
            float d = sqrtf(fmaxf(s, 1e-12f));
            g_D[pi * NC + pj] = d;
            g_D[pj * NC + pi] = d;
        }
        if (bid == 0 && tid < NC) {
            g_D[tid * NC + tid] = 1e-6f;                   // sqrt(clip(0,1e-12))
            g_present[tid] = (s_first[tid] != INVALID) ? 1 : 0;
        }
    } else {
        // ================= HIST ROLE (ua only) ===============================
        {
            int4 z = make_int4(0, 0, 0, 0);
            int4* h4 = (int4*)sH;
            #pragma unroll
            for (int r = 0; r < 4; r++) h4[r * 256 + tid] = z;
        }
        __syncthreads();

        const unsigned* uw = (const unsigned*)ua;
        const int hb   = bid - NPAIR;
        const int nbh  = nblocks - NPAIR;

        unsigned du = 0u;
        {
            int w = 2 * tid + 1;
            if (w < 3 * T) du = uw[w];      // int64 => all odd words zero
        }
        const int t0 = (hb * 256 + tid) * TPT;
        int4 q[12];
        const bool vec_ok = (t0 + TPT <= T);
        if (vec_ok) {
            const int4* p = (const int4*)(uw + 3 * (size_t)t0);
            #pragma unroll
            for (int r = 0; r < 12; r++) q[r] = __ldg(p + r);
        }
        if (du) s_nz = 1;
        __syncthreads();
        const int ua64 = (s_nz == 0);

        if (!ua64 && vec_ok) {
            const int* qi = (const int*)q;
            #pragma unroll
            for (int k = 0; k < TPT; k++) {
                int bin = ((qi[3*k] & 15) << 8) | ((qi[3*k+1] & 15) << 4)
                        | (qi[3*k+2] & 15);
                atomicAdd(&sH[bin], 1);
            }
        } else {
            #pragma unroll 4
            for (int k = 0; k < TPT; k++) {
                int t = t0 + k;
                if (t < T) {
                    int a, p, n;
                    if (ua64) {
                        size_t b = (size_t)6 * t;
                        a = (int)__ldg(uw + b); p = (int)__ldg(uw + b + 2);
                        n = (int)__ldg(uw + b + 4);
                    } else {
                        size_t b = (size_t)3 * t;
                        a = (int)__ldg(uw + b); p = (int)__ldg(uw + b + 1);
                        n = (int)__ldg(uw + b + 2);
                    }
                    atomicAdd(&sH[((a & 15) << 8) | ((p & 15) << 4) | (n & 15)], 1);
                }
            }
        }
        for (int t = nbh * 256 * TPT + hb * 256 + tid; t < T; t += nbh * 256) {
            int a, p, n;
            if (ua64) {
                size_t b = (size_t)6 * t;
                a = (int)__ldg(uw + b); p = (int)__ldg(uw + b + 2);
                n = (int)__ldg(uw + b + 4);
            } else {
                size_t b = (size_t)3 * t;
                a = (int)__ldg(uw + b); p = (int)__ldg(uw + b + 1);
                n = (int)__ldg(uw + b + 2);
            }
            atomicAdd(&sH[((a & 15) << 8) | ((p & 15) << 4) | (n & 15)], 1);
        }
        __syncthreads();

        // flush nonzero bins (spread REDG, fire-and-forget)
        #pragma unroll
        for (int r = 0; r < 16; r++) {
            int idx = r * 256 + tid;
            int v = sH[idx];
            if (v) atomicAdd(&g_hist[idx], v);
        }
    }

    // ================= done counter; last block finalizes ====================
    __threadfence();
    __syncthreads();
    if (tid == 0) {
        unsigned d = atomicAdd(&g_done, 1u);
        if (d == (unsigned)(nblocks - 1)) s_last = 1;
    }
    __syncthreads();
    if (!s_last) return;

    // ---- finalize: FRONT-BATCH all reads (one L2 round-trip), THEN stores.
    __threadfence();
    int cnt[16];
    #pragma unroll
    for (int r = 0; r < 16; r++)
        cnt[r] = __ldcg(&g_hist[r * 256 + tid]);     // 16 independent loads
    float dv = __ldcg(&g_D[tid]);
    int   pv = (tid < NC) ? __ldcg(&g_present[tid]) : 0;

    #pragma unroll
    for (int r = 0; r < 16; r++)                     // reset for graph replay
        g_hist[r * 256 + tid] = 0;

    sDf[tid] = dv;
    if (tid < NC) s_first[tid] = pv;                 // reuse as presence
    __syncthreads();

    float rk = 0.0f, pr = 0.0f, cv = 0.0f;
    #pragma unroll
    for (int r = 0; r < 16; r++) {
        int c = cnt[r];
        if (c) {
            int idx = r * 256 + tid;
            int a = idx >> 8, p = (idx >> 4) & 15, n = idx & 15;
            if (s_first[a] && s_first[p] && s_first[n]) {
                float dap = sDf[(a << 4) | p];
                float dan = sDf[(a << 4) | n];
                float fc  = (float)c;
                rk += fc * fmaxf(dap - dan + MARGIN, 0.0f);
                float sap = 1.0f / (dap + 1.0f);
                float san = 1.0f / (dan + 1.0f);
                pr += fc * (-logf(sap / (sap + san) + EPS));
                cv += fc;
            }
        }
    }
    #pragma unroll
    for (int o = 16; o > 0; o >>= 1) {
        rk += __shfl_xor_sync(~0u, rk, o);
        pr += __shfl_xor_sync(~0u, pr, o);
        cv += __shfl_xor_sync(~0u, cv, o);
    }
    int w = tid >> 5;
    if ((tid & 31) == 0) { srk[w] = rk; spr[w] = pr; scv[w] = cv; }
    __syncthreads();
    if (tid == 0) {
        float R = 0.0f, P = 0.0f, V = 0.0f;
        #pragma unroll
        for (int k = 0; k < 8; k++) { R += srk[k]; P += spr[k]; V += scv[k]; }
        float nv = fmaxf(V, 1.0f);
        float lh = R / nv;
        float lp = P / nv;
        out[0] = lh + lp;
        out[1] = lh;
        out[2] = lp;
        g_done = 0u;                                 // reset for graph replay
    }
}

// ---------------- launch ----------------
// Inputs: 0 preds_mat(f32), 1 preds_sub(f32), 2 inputs(f32 B*D),
// 3 targets_mat(int, B), 4 targets_sub(int, B), 5 user_answers(int, T*3)
extern "C" void kernel_launch(void* const* d_in, const int* in_sizes, int n_in,
                              void* d_out, int out_size) {
    const float* inputs = (const float*)d_in[2];
    const void*  tm     = d_in[3];
    const void*  ua     = d_in[5];
    int n_tm = in_sizes[3];
    int T    = in_sizes[5] / 3;
    int D    = in_sizes[2] / n_tm;

    int nbh = (T + 256 * TPT - 1) / (256 * TPT);     // hist blocks (25 @ T=100k)
    if (nbh < 1) nbh = 1;
    if (nbh > 28) nbh = 28;                          // keep grid <= 148 (1 wave)
    int nb = NPAIR + nbh;
    fused<<<nb, 256>>>(inputs, tm, ua, n_tm, T, D, nb, (float*)d_out);
}

// round 14
// speedup vs baseline: 1.4464x; 1.4464x over previous
#include <cuda_runtime.h>
#include <math.h>

#define NC 16
#define MARGIN 0.3f
#define INVALID 0x7fffffff
#define NBIN 4096            // 16^3 class combos
#define NPAIR 120            // 16*15/2 unordered pairs
#define TPT 16               // triples per hist thread

// ---------------- device-global scratch (zero-init; K2 resets) -----------------
__device__ int      g_hist[NBIN];
__device__ float    g_D[NC * NC];
__device__ int      g_present[NC];
__device__ float    g_sum_rank;
__device__ float    g_sum_per;
__device__ float    g_sum_cnt;
__device__ unsigned g_done;

// Dedup-min: within one load slot the global index rises with lane, so the
// lowest-lane peer holding a given class value owns the warp minimum.
__device__ __forceinline__ void first_update(unsigned w, int i, int* s_first) {
    unsigned peers = __match_any_sync(0xffffffffu, w);
    int leader = __ffs(peers) - 1;
    if (((int)(threadIdx.x & 31) == leader) && w < (unsigned)NC)
        atomicMin(&s_first[w], i);
}

// ---------------- K1: disjoint roles, NO tail work ------------------------------
// Pair blocks (0..119): first_idx scan + one distance pair -> g_D / g_present.
// Hist blocks (120..): histogram triples into g_hist. No fences, no counters.
__global__ __launch_bounds__(256) void k1(
    const float* __restrict__ inputs, const void* __restrict__ tm,
    const void* __restrict__ ua, int n_tm, int T, int D, int nblocks)
{
    __shared__ int   sH[NBIN];             // hist role only (16 KB)
    __shared__ int   s_first[NC];
    __shared__ int   s_nz;
    __shared__ float s_part[8];

    const int tid = threadIdx.x;
    const int bid = blockIdx.x;
    if (tid == 0) s_nz = 0;

    if (bid < NPAIR) {
        // ================= PAIR ROLE =================
        if (tid < NC) s_first[tid] = INVALID;
        __syncthreads();

        const unsigned* tw = (const unsigned*)tm;

        unsigned det = 0u;
        {
            int w0 = 2 * tid + 1;
            if (w0 < n_tm) det = tw[w0];
            int w1 = w0 + 512;
            if (w1 < n_tm) det |= tw[w1];
        }
        unsigned wv[16];
        #pragma unroll
        for (int r = 0; r < 16; r++) {
            int i = r * 256 + tid;
            wv[r] = (i < n_tm) ? tw[i] : ~0u;
        }
        if (det) s_nz = 1;
        __syncthreads();

        if (s_nz) {          // int32: speculative loads are the real data
            #pragma unroll
            for (int r = 0; r < 16; r++) first_update(wv[r], r * 256 + tid, s_first);
            for (int i = 4096 + tid; i < n_tm; i += 256)
                first_update(tw[i], i, s_first);
        } else {             // int64: low words at stride 2
            for (int i = tid; i < n_tm; i += 256)
                first_update(tw[2 * i], i, s_first);
        }
        __syncthreads();

        int b = bid, pi = 0, rem = b, cnt = NC - 1;
        while (rem >= cnt) { rem -= cnt; cnt--; pi++; }
        int pj = pi + 1 + rem;
        int fi = s_first[pi]; if (fi == INVALID) fi = 0;   // argmax all-false==0
        int fj = s_first[pj]; if (fj == INVALID) fj = 0;

        float acc = 0.0f;
        const float* ra = inputs + (size_t)fi * D;
        const float* rb = inputs + (size_t)fj * D;
        for (int base = 0; base < D; base += 1024) {
            int k = base + tid * 4;
            if (k + 4 <= D) {
                float4 x = __ldg((const float4*)(ra + k));
                float4 y = __ldg((const float4*)(rb + k));
                float d0 = x.x - y.x, d1 = x.y - y.y;
                float d2 = x.z - y.z, d3 = x.w - y.w;
                acc = fmaf(d0, d0, acc); acc = fmaf(d1, d1, acc);
                acc = fmaf(d2, d2, acc); acc = fmaf(d3, d3, acc);
            } else {
                for (int q = k; q < D && q < k + 4; q++) {
                    float d = __ldg(ra + q) - __ldg(rb + q);
                    acc = fmaf(d, d, acc);
                }
            }
        }
        #pragma unroll
        for (int o = 16; o > 0; o >>= 1) acc += __shfl_xor_sync(~0u, acc, o);
        if ((tid & 31) == 0) s_part[tid >> 5] = acc;
        __syncthreads();
        if (tid == 0) {
            float s = 0.0f;
            #pragma unroll
            for (int k = 0; k < 8; k++) s += s_part[k];
            float d = sqrtf(fmaxf(s, 1e-12f));
            g_D[pi * NC + pj] = d;
            g_D[pj * NC + pi] = d;
        }
        if (bid == 0 && tid < NC) {
            g_D[tid * NC + tid] = 1e-6f;                   // sqrt(clip(0,1e-12))
            g_present[tid] = (s_first[tid] != INVALID) ? 1 : 0;
        }
    } else {
        // ================= HIST ROLE =================
        {
            int4 z = make_int4(0, 0, 0, 0);
            int4* h4 = (int4*)sH;
            #pragma unroll
            for (int r = 0; r < 4; r++) h4[r * 256 + tid] = z;
        }
        __syncthreads();

        const unsigned* uw = (const unsigned*)ua;
        const int hb  = bid - NPAIR;
        const int nbh = nblocks - NPAIR;

        unsigned du = 0u;
        {
            int w = 2 * tid + 1;
            if (w < 3 * T) du = uw[w];      // int64 => all odd words zero
        }
        const int t0 = (hb * 256 + tid) * TPT;
        int4 q[12];
        const bool vec_ok = (t0 + TPT <= T);
        if (vec_ok) {
            const int4* p = (const int4*)(uw + 3 * (size_t)t0);
            #pragma unroll
            for (int r = 0; r < 12; r++) q[r] = __ldg(p + r);
        }
        if (du) s_nz = 1;
        __syncthreads();
        const int ua64 = (s_nz == 0);

        if (!ua64 && vec_ok) {
            const int* qi = (const int*)q;
            #pragma unroll
            for (int k = 0; k < TPT; k++) {
                int bin = ((qi[3*k] & 15) << 8) | ((qi[3*k+1] & 15) << 4)
                        | (qi[3*k+2] & 15);
                atomicAdd(&sH[bin], 1);
            }
        } else {
            #pragma unroll 4
            for (int k = 0; k < TPT; k++) {
                int t = t0 + k;
                if (t < T) {
                    int a, p, n;
                    if (ua64) {
                        size_t b = (size_t)6 * t;
                        a = (int)__ldg(uw + b); p = (int)__ldg(uw + b + 2);
                        n = (int)__ldg(uw + b + 4);
                    } else {
                        size_t b = (size_t)3 * t;
                        a = (int)__ldg(uw + b); p = (int)__ldg(uw + b + 1);
                        n = (int)__ldg(uw + b + 2);
                    }
                    atomicAdd(&sH[((a & 15) << 8) | ((p & 15) << 4) | (n & 15)], 1);
                }
            }
        }
        for (int t = nbh * 256 * TPT + hb * 256 + tid; t < T; t += nbh * 256) {
            int a, p, n;
            if (ua64) {
                size_t b = (size_t)6 * t;
                a = (int)__ldg(uw + b); p = (int)__ldg(uw + b + 2);
                n = (int)__ldg(uw + b + 4);
            } else {
                size_t b = (size_t)3 * t;
                a = (int)__ldg(uw + b); p = (int)__ldg(uw + b + 1);
                n = (int)__ldg(uw + b + 2);
            }
            atomicAdd(&sH[((a & 15) << 8) | ((p & 15) << 4) | (n & 15)], 1);
        }
        __syncthreads();

        // flush nonzero bins (spread REDG, fire-and-forget; visibility is
        // guaranteed by the kernel boundary)
        #pragma unroll
        for (int r = 0; r < 16; r++) {
            int idx = r * 256 + tid;
            int v = sH[idx];
            if (v) atomicAdd(&g_hist[idx], v);
        }
    }
}

// ---------------- K2: 16 blocks finalize (256 bins each, 1 MUFU/bin) -----------
// Block a handles bins [a*256, a*256+256): dap = D[a][p], dan = D[a][n] — both
// from D-row a, so log(dan+1) is a 16-entry table per block.
//   -log(p_ap + EPS) ~= log(dap+dan+2) - log(dan+1)   (EPS ~1e-8 << p_ap)
__global__ __launch_bounds__(256) void k2(float* __restrict__ out) {
    __shared__ float sDa[NC], sL1[NC];
    __shared__ int   sP[NC];
    __shared__ int   s_last;
    __shared__ float srk[8], spr[8], scv[8];

    const int tid = threadIdx.x;
    const int a   = blockIdx.x;
    if (tid == 0) s_last = 0;

    // front batch: this block's 256 bin counts + row a of D + presence
    int cnt = __ldcg(&g_hist[a * 256 + tid]);
    float dv = 0.0f; int pv = 0;
    if (tid < NC) {
        dv = __ldcg(&g_D[a * NC + tid]);
        pv = __ldcg(&g_present[tid]);
    }
    g_hist[a * 256 + tid] = 0;                       // reset for graph replay

    if (tid < NC) {
        sDa[tid] = dv;
        sP[tid]  = pv;
        sL1[tid] = __logf(dv + 1.0f);
    }
    __syncthreads();

    const int p = tid >> 4, n = tid & 15;
    float rk = 0.0f, pr = 0.0f, cv = 0.0f;
    if (cnt && sP[a] && sP[p] && sP[n]) {
        float dap = sDa[p];
        float dan = sDa[n];
        float fc  = (float)cnt;
        rk = fc * fmaxf(dap - dan + MARGIN, 0.0f);
        pr = fc * (__logf(dap + dan + 2.0f) - sL1[n]);
        cv = fc;
    }
    #pragma unroll
    for (int o = 16; o > 0; o >>= 1) {
        rk += __shfl_xor_sync(~0u, rk, o);
        pr += __shfl_xor_sync(~0u, pr, o);
        cv += __shfl_xor_sync(~0u, cv, o);
    }
    int w = tid >> 5;
    if ((tid & 31) == 0) { srk[w] = rk; spr[w] = pr; scv[w] = cv; }
    __syncthreads();

    if (tid == 0) {
        float R = 0.0f, P = 0.0f, V = 0.0f;
        #pragma unroll
        for (int k = 0; k < 8; k++) { R += srk[k]; P += spr[k]; V += scv[k]; }
        atomicAdd(&g_sum_rank, R);
        atomicAdd(&g_sum_per,  P);
        atomicAdd(&g_sum_cnt,  V);
        __threadfence();
        unsigned d = atomicAdd(&g_done, 1u);
        if (d == (unsigned)(NC - 1)) {
            float sr = atomicAdd(&g_sum_rank, 0.0f);
            float sp = atomicAdd(&g_sum_per,  0.0f);
            float sv = atomicAdd(&g_sum_cnt,  0.0f);
            float nv = fmaxf(sv, 1.0f);
            float lh = sr / nv;
            float lp = sp / nv;
            out[0] = lh + lp;
            out[1] = lh;
            out[2] = lp;
            g_sum_rank = 0.0f; g_sum_per = 0.0f; g_sum_cnt = 0.0f;
            g_done = 0u;                             // reset for graph replay
        }
    }
}

// ---------------- launch ----------------
// Inputs: 0 preds_mat(f32), 1 preds_sub(f32), 2 inputs(f32 B*D),
// 3 targets_mat(int, B), 4 targets_sub(int, B), 5 user_answers(int, T*3)
extern "C" void kernel_launch(void* const* d_in, const int* in_sizes, int n_in,
                              void* d_out, int out_size) {
    const float* inputs = (const float*)d_in[2];
    const void*  tm     = d_in[3];
    const void*  ua     = d_in[5];
    int n_tm = in_sizes[3];
    int T    = in_sizes[5] / 3;
    int D    = in_sizes[2] / n_tm;

    int nbh = (T + 256 * TPT - 1) / (256 * TPT);     // hist blocks (25 @ T=100k)
    if (nbh < 1) nbh = 1;
    if (nbh > 28) nbh = 28;                          // keep grid <= 148 (1 wave)
    int nb = NPAIR + nbh;
    k1<<<nb, 256>>>(inputs, tm, ua, n_tm, T, D, nb);
    k2<<<NC, 256>>>((float*)d_out);
}